// round 7
// baseline (speedup 1.0000x reference)
#include <cuda_runtime.h>

// ---------------------------------------------------------------------------
// 3-layer GCN persistent megakernel, round 7:
//  - warp-aggregated CSR bump allocation (1 atomic per warp, not per node)
//  - 6 CTAs/SM (888 CTAs, 40-reg cap); GEMM micro-tile 2 rows/thread
//  - dynamic chunked scheduling for gather1/gather2 (tail elimination)
//  - warp-parallel edge-dtype detection
// ---------------------------------------------------------------------------

#define NMAX 100000
#define EMAX 1600000
#define CSRMAX (EMAX + 4 * NMAX)
#define NB  888          // 148 SMs x 6 CTAs
#define TPB 256
#define NTH (NB * TPB)

__device__ unsigned g_bar;        // zero-init; restored to 0 at exit
__device__ int   g_alloc;         // restored at exit
__device__ int   g_work[8];       // tile/chunk counters; restored at exit
__device__ int   g_deg[NMAX];     // zeroed by previous run's final phase
__device__ int   g_rowptr[NMAX];
__device__ int   g_cursor[NMAX];  // zeroed by previous run's gather1 phase
__device__ float g_dis[NMAX];
__device__ __align__(16) int g_csr[CSRMAX];   // src indices; pads = dst itself
__device__ float g_h[(size_t)NMAX * 64];
__device__ float g_o[(size_t)NMAX * 64];

struct SM {
    __align__(16) float w[4096];
    int tile;
    int is64;
};

__device__ __forceinline__ float fast_tanh(float x) {
    float y;
    asm("tanh.approx.f32 %0, %1;" : "=f"(y) : "f"(x));
    return y;
}

__device__ __forceinline__ void gsync(unsigned target) {
    __syncthreads();
    if (threadIdx.x == 0) {
        __threadfence();
        atomicAdd(&g_bar, 1u);
        while (*((volatile unsigned*)&g_bar) < target) __nanosleep(64);
    }
    __syncthreads();
}

__device__ __forceinline__ int edge_at(const void* ei, size_t idx, int is64) {
    if (is64) return (int)((const long long*)ei)[idx];
    return ((const int*)ei)[idx];
}

// ---- GEMM: O[N,M] = dis[row] * (X[N,K] @ W[K,M]), dynamic 32-row tiles -----
template <int K, int M>
__device__ void gemm_phase(const float* __restrict__ X, const float* __restrict__ W,
                           float* __restrict__ O, int N, SM* sm, int workid) {
    constexpr int TN = M / 16;
    for (int i = threadIdx.x; i < K * M; i += TPB) sm->w[i] = W[i];
    int cg = threadIdx.x & 15;
    int rg = threadIdx.x >> 4;
    int tiles = (N + 31) >> 5;
    const float4* __restrict__ X4 = (const float4*)X;
    for (;;) {
        __syncthreads();
        if (threadIdx.x == 0) sm->tile = atomicAdd(&g_work[workid], 1);
        __syncthreads();
        int tile = sm->tile;
        if (tile >= tiles) break;
        int row0 = tile * 32 + rg * 2;
        bool full = (row0 + 1 < N);
        float acc[2][TN];
        #pragma unroll
        for (int r = 0; r < 2; r++)
            #pragma unroll
            for (int t = 0; t < TN; t++) acc[r][t] = 0.f;
        #pragma unroll 2
        for (int k4 = 0; k4 < K / 4; k4++) {
            float4 xv[2];
            #pragma unroll
            for (int r = 0; r < 2; r++) {
                int row = row0 + r;
                if (full || row < N) xv[r] = __ldg(&X4[(size_t)row * (K / 4) + k4]);
                else xv[r] = make_float4(0.f, 0.f, 0.f, 0.f);
            }
            #pragma unroll
            for (int kk = 0; kk < 4; kk++) {
                int k = k4 * 4 + kk;
                float wv[TN];
                if (TN == 4) {
                    float4 wq = ((const float4*)sm->w)[k * (M / 4) + cg];
                    wv[0] = wq.x; wv[1] = wq.y; wv[2] = wq.z; wv[3] = wq.w;
                } else {
                    float2 wq = ((const float2*)sm->w)[k * (M / 2) + cg];
                    wv[0] = wq.x; wv[1] = wq.y;
                }
                float xs[2] = { kk == 0 ? xv[0].x : kk == 1 ? xv[0].y : kk == 2 ? xv[0].z : xv[0].w,
                                kk == 0 ? xv[1].x : kk == 1 ? xv[1].y : kk == 2 ? xv[1].z : xv[1].w };
                #pragma unroll
                for (int t = 0; t < TN; t++)
                    #pragma unroll
                    for (int r = 0; r < 2; r++)
                        acc[r][t] = fmaf(xs[r], wv[t], acc[r][t]);
            }
        }
        #pragma unroll
        for (int r = 0; r < 2; r++) {
            int row = row0 + r;
            if (row < N) {
                float dsr = g_dis[row];
                #pragma unroll
                for (int t = 0; t < TN; t++)
                    O[(size_t)row * M + cg * TN + t] = acc[r][t] * dsr;
            }
        }
    }
}

// ---- gather core: plain sum of pre-scaled features -------------------------
template <int L>
__device__ __forceinline__ float4 gather_sum(const float4* __restrict__ Hv,
                                             const int4* __restrict__ C4,
                                             int pc, int lane) {
    float4 acc = make_float4(0.f, 0.f, 0.f, 0.f);
    for (int j = 0; j < pc; j++) {
        int4 a = __ldg(&C4[j]);
        float4 h0 = __ldg(&Hv[(size_t)a.x * L + lane]);
        float4 h1 = __ldg(&Hv[(size_t)a.y * L + lane]);
        float4 h2 = __ldg(&Hv[(size_t)a.z * L + lane]);
        float4 h3 = __ldg(&Hv[(size_t)a.w * L + lane]);
        acc.x += (h0.x + h1.x) + (h2.x + h3.x);
        acc.y += (h0.y + h1.y) + (h2.y + h3.y);
        acc.z += (h0.z + h1.z) + (h2.z + h3.z);
        acc.w += (h0.w + h1.w) + (h2.w + h3.w);
    }
    return acc;
}

// ---------------------------------------------------------------------------
__global__ void __launch_bounds__(TPB, 6) k_mega(
        const float* __restrict__ x, const void* __restrict__ ei,
        const float* __restrict__ W1, const float* __restrict__ b1,
        const float* __restrict__ W2, const float* __restrict__ b2,
        const float* __restrict__ W3, const float* __restrict__ b3,
        float* __restrict__ out, int N, int E) {
    __shared__ SM sm;
    int gtid = blockIdx.x * TPB + threadIdx.x;
    int lane = threadIdx.x & 31;

    // warp-parallel dtype detect (first 64 int64 values), per block
    if (threadIdx.x < 32) {
        const long long* p = (const long long*)ei;
        long long v0 = p[threadIdx.x], v1 = p[32 + threadIdx.x];
        int ok = (v0 >= 0 && v0 < (long long)N && v1 >= 0 && v1 < (long long)N);
        unsigned m = __ballot_sync(0xffffffffu, ok);
        if (threadIdx.x == 0) sm.is64 = (m == 0xffffffffu);
    }
    __syncthreads();
    int is64 = sm.is64;

    // Phase A: degree histogram (deg pre-zeroed by previous run)
    for (int e = gtid; e < E; e += NTH)
        atomicAdd(&g_deg[edge_at(ei, (size_t)E + e, is64)], 1);
    gsync(1u * NB);

    // Phase B: warp-aggregated bump allocation + dis + pad entries (= self)
    {
        int nround = ((N + NTH - 1) / NTH) * NTH;
        for (int i = gtid; i < nround; i += NTH) {
            int d = (i < N) ? g_deg[i] : 0;
            int pad = (i < N) ? ((d + 3) & ~3) : 0;
            int incl = pad;
            #pragma unroll
            for (int off = 1; off < 32; off <<= 1) {
                int v = __shfl_up_sync(0xffffffffu, incl, off);
                if (lane >= off) incl += v;
            }
            int total = __shfl_sync(0xffffffffu, incl, 31);
            int base;
            if (lane == 31) base = atomicAdd(&g_alloc, total);
            base = __shfl_sync(0xffffffffu, base, 31);
            if (i < N) {
                int st = base + incl - pad;
                g_rowptr[i] = st;
                g_dis[i] = rsqrtf((float)(d + 1));
                for (int j = d; j < pad; j++) g_csr[st + j] = i;
            }
        }
    }
    gsync(2u * NB);

    // Phase C: GEMM1 (x @ W1, scaled by dis) + CSR fill (independent work)
    gemm_phase<64, 64>(x, W1, g_h, N, &sm, 0);
    for (int e = gtid; e < E; e += NTH) {
        int s = edge_at(ei, e, is64);
        int d = edge_at(ei, (size_t)E + e, is64);
        int pos = atomicAdd(&g_cursor[d], 1);
        g_csr[g_rowptr[d] + pos] = s;
    }
    gsync(3u * NB);

    // Phase D: gather1 -> o1 = tanh(dis*(sum + (1-pad)*hs_self) + b1)
    for (int i = gtid; i < N; i += NTH) g_cursor[i] = 0;   // re-zero for next run
    {
        const float4* Hv = (const float4*)g_h;
        const float4* bv4 = (const float4*)b1;
        const int CH = TPB * 2;
        long long items = (long long)N * 16;
        int nchunks = (int)((items + CH - 1) / CH);
        for (;;) {
            __syncthreads();
            if (threadIdx.x == 0) sm.tile = atomicAdd(&g_work[2], 1);
            __syncthreads();
            int c = sm.tile;
            if (c >= nchunks) break;
            #pragma unroll
            for (int r = 0; r < 2; r++) {
                long long it = (long long)c * CH + r * TPB + threadIdx.x;
                if (it >= items) break;
                int node = (int)(it >> 4);
                int ln = (int)(it & 15);
                int d = g_deg[node];
                int pc = (d + 3) >> 2;
                float coef = 1.0f - (float)((pc << 2) - d);
                float4 acc = gather_sum<16>(Hv, (const int4*)(g_csr + g_rowptr[node]), pc, ln);
                float4 hs = __ldg(&Hv[(size_t)node * 16 + ln]);
                acc.x = fmaf(hs.x, coef, acc.x);
                acc.y = fmaf(hs.y, coef, acc.y);
                acc.z = fmaf(hs.z, coef, acc.z);
                acc.w = fmaf(hs.w, coef, acc.w);
                float dsn = g_dis[node];
                float4 bv = __ldg(&bv4[ln]);
                float4 o;
                o.x = fast_tanh(fmaf(acc.x, dsn, bv.x));
                o.y = fast_tanh(fmaf(acc.y, dsn, bv.y));
                o.z = fast_tanh(fmaf(acc.z, dsn, bv.z));
                o.w = fast_tanh(fmaf(acc.w, dsn, bv.w));
                ((float4*)g_o)[(size_t)node * 16 + ln] = o;
            }
        }
    }
    gsync(4u * NB);

    // Phase E: GEMM2 (o1 @ W2, scaled by dis) -> g_h
    gemm_phase<64, 32>(g_o, W2, g_h, N, &sm, 1);
    gsync(5u * NB);

    // Phase F: gather2 + tanh + fused projection; store hs3 = dis*(o2.W3)
    {
        const float4* Hv = (const float4*)g_h;
        const float4* bv4 = (const float4*)b2;
        const float4* w34 = (const float4*)W3;
        int lane8 = lane & 7;
        float4 w3 = __ldg(&w34[lane8]);
        const int CH = TPB * 2;
        long long items = (long long)N * 8;
        int nchunks = (int)((items + CH - 1) / CH);
        for (;;) {
            __syncthreads();
            if (threadIdx.x == 0) sm.tile = atomicAdd(&g_work[3], 1);
            __syncthreads();
            int c = sm.tile;
            if (c >= nchunks) break;
            #pragma unroll
            for (int r = 0; r < 2; r++) {
                long long it = (long long)c * CH + r * TPB + threadIdx.x;
                bool act = (it < items);
                float partial = 0.f;
                int node = 0;
                float dsn = 0.f;
                if (act) {
                    node = (int)(it >> 3);
                    int l = (int)(it & 7);
                    int d = g_deg[node];
                    int pc = (d + 3) >> 2;
                    float coef = 1.0f - (float)((pc << 2) - d);
                    float4 acc = gather_sum<8>(Hv, (const int4*)(g_csr + g_rowptr[node]), pc, l);
                    float4 hs = __ldg(&Hv[(size_t)node * 8 + l]);
                    acc.x = fmaf(hs.x, coef, acc.x);
                    acc.y = fmaf(hs.y, coef, acc.y);
                    acc.z = fmaf(hs.z, coef, acc.z);
                    acc.w = fmaf(hs.w, coef, acc.w);
                    dsn = g_dis[node];
                    float4 bv = __ldg(&bv4[l]);
                    float4 o;
                    o.x = fast_tanh(fmaf(acc.x, dsn, bv.x));
                    o.y = fast_tanh(fmaf(acc.y, dsn, bv.y));
                    o.z = fast_tanh(fmaf(acc.z, dsn, bv.z));
                    o.w = fast_tanh(fmaf(acc.w, dsn, bv.w));
                    partial = o.x * w3.x + o.y * w3.y + o.z * w3.z + o.w * w3.w;
                }
                partial += __shfl_down_sync(0xffffffffu, partial, 4, 8);
                partial += __shfl_down_sync(0xffffffffu, partial, 2, 8);
                partial += __shfl_down_sync(0xffffffffu, partial, 1, 8);
                if (act && lane8 == 0) g_o[node] = dsn * partial;
            }
        }
    }
    gsync(6u * NB);

    // Phase G: scalar gather3; out = dis*(sum + hs3_self) + b3; zero deg
    {
        float bb = __ldg(b3);
        int wg = gtid >> 5;
        for (int n = wg; n < N; n += (NTH >> 5)) {
            int start = g_rowptr[n];
            int c = g_deg[n];
            float acc = 0.f;
            for (int j = lane; j < c; j += 32)
                acc += __ldg(&g_o[g_csr[start + j]]);
            #pragma unroll
            for (int off = 16; off; off >>= 1)
                acc += __shfl_down_sync(0xffffffffu, acc, off);
            if (lane == 0) {
                out[n] = fmaf(g_dis[n], acc + g_o[n], bb);
                g_deg[n] = 0;                    // restore invariant
            }
        }
    }

    // final arrival: last CTA resets counters for next graph replay
    __syncthreads();
    if (threadIdx.x == 0) {
        __threadfence();
        unsigned v = atomicAdd(&g_bar, 1u);
        if (v == 7u * NB - 1u) {
            g_bar = 0u; g_alloc = 0;
            g_work[0] = 0; g_work[1] = 0; g_work[2] = 0; g_work[3] = 0;
        }
    }
}

// ---------------------------------------------------------------------------
extern "C" void kernel_launch(void* const* d_in, const int* in_sizes, int n_in,
                              void* d_out, int out_size) {
    const float* x  = (const float*)d_in[0];
    const void*  ei = d_in[1];
    const float* W1 = (const float*)d_in[2];
    const float* b1 = (const float*)d_in[3];
    const float* W2 = (const float*)d_in[4];
    const float* b2 = (const float*)d_in[5];
    const float* W3 = (const float*)d_in[6];
    const float* b3 = (const float*)d_in[7];
    float* out = (float*)d_out;

    int N = in_sizes[0] / 64;
    int E = in_sizes[1] / 2;

    k_mega<<<NB, TPB>>>(x, ei, W1, b1, W2, b2, W3, b3, out, N, E);
}

// round 8
// speedup vs baseline: 1.5802x; 1.5802x over previous
#include <cuda_runtime.h>

// ---------------------------------------------------------------------------
// 3-layer GCN persistent megakernel, round 8 (= round 6 structure + isolated
// wins from round 7, dynamic-chunk scheduling reverted):
//  - pre-scaled features (dis folded into GEMM epilogue), 4B CSR entries
//  - warp-aggregated CSR bump allocation (1 atomic per warp)
//  - static free-running gather loops (no intra-phase barriers)
//  - 5 CTAs/SM, 4-row GEMM micro-tiles, dynamic GEMM tile scheduling
//  - deferred zeroing across graph replays
// ---------------------------------------------------------------------------

#define NMAX 100000
#define EMAX 1600000
#define CSRMAX (EMAX + 4 * NMAX)
#define NB  740          // 148 SMs x 5 CTAs
#define TPB 256
#define NTH (NB * TPB)

__device__ unsigned g_bar;        // zero-init; restored to 0 at exit
__device__ int   g_alloc;         // restored at exit
__device__ int   g_work[8];       // GEMM tile counters; restored at exit
__device__ int   g_deg[NMAX];     // zeroed by previous run's final phase
__device__ int   g_rowptr[NMAX];
__device__ int   g_cursor[NMAX];  // zeroed by previous run's gather1 phase
__device__ float g_dis[NMAX];
__device__ __align__(16) int g_csr[CSRMAX];   // src indices; pads = dst itself
__device__ float g_h[(size_t)NMAX * 64];
__device__ float g_o[(size_t)NMAX * 64];

struct SM {
    __align__(16) float w[4096];
    int tile;
    int is64;
};

__device__ __forceinline__ float fast_tanh(float x) {
    float y;
    asm("tanh.approx.f32 %0, %1;" : "=f"(y) : "f"(x));
    return y;
}

__device__ __forceinline__ void gsync(unsigned target) {
    __syncthreads();
    if (threadIdx.x == 0) {
        __threadfence();
        atomicAdd(&g_bar, 1u);
        while (*((volatile unsigned*)&g_bar) < target) __nanosleep(64);
    }
    __syncthreads();
}

__device__ __forceinline__ int edge_at(const void* ei, size_t idx, int is64) {
    if (is64) return (int)((const long long*)ei)[idx];
    return ((const int*)ei)[idx];
}

// ---- GEMM: O[N,M] = dis[row] * (X[N,K] @ W[K,M]), dynamic 64-row tiles -----
template <int K, int M>
__device__ void gemm_phase(const float* __restrict__ X, const float* __restrict__ W,
                           float* __restrict__ O, int N, SM* sm, int workid) {
    constexpr int TN = M / 16;
    for (int i = threadIdx.x; i < K * M; i += TPB) sm->w[i] = W[i];
    int cg = threadIdx.x & 15;
    int rg = threadIdx.x >> 4;
    int tiles = (N + 63) >> 6;
    const float4* __restrict__ X4 = (const float4*)X;
    for (;;) {
        __syncthreads();
        if (threadIdx.x == 0) sm->tile = atomicAdd(&g_work[workid], 1);
        __syncthreads();
        int tile = sm->tile;
        if (tile >= tiles) break;
        int row0 = tile * 64 + rg * 4;
        bool full = (row0 + 3 < N);
        float acc[4][TN];
        #pragma unroll
        for (int r = 0; r < 4; r++)
            #pragma unroll
            for (int t = 0; t < TN; t++) acc[r][t] = 0.f;
        #pragma unroll 2
        for (int k4 = 0; k4 < K / 4; k4++) {
            float4 xv[4];
            #pragma unroll
            for (int r = 0; r < 4; r++) {
                int row = row0 + r;
                if (full || row < N) xv[r] = __ldg(&X4[(size_t)row * (K / 4) + k4]);
                else xv[r] = make_float4(0.f, 0.f, 0.f, 0.f);
            }
            #pragma unroll
            for (int kk = 0; kk < 4; kk++) {
                int k = k4 * 4 + kk;
                float wv[TN];
                if (TN == 4) {
                    float4 wq = ((const float4*)sm->w)[k * (M / 4) + cg];
                    wv[0] = wq.x; wv[1] = wq.y; wv[2] = wq.z; wv[3] = wq.w;
                } else {
                    float2 wq = ((const float2*)sm->w)[k * (M / 2) + cg];
                    wv[0] = wq.x; wv[1] = wq.y;
                }
                float xs[4] = { kk == 0 ? xv[0].x : kk == 1 ? xv[0].y : kk == 2 ? xv[0].z : xv[0].w,
                                kk == 0 ? xv[1].x : kk == 1 ? xv[1].y : kk == 2 ? xv[1].z : xv[1].w,
                                kk == 0 ? xv[2].x : kk == 1 ? xv[2].y : kk == 2 ? xv[2].z : xv[2].w,
                                kk == 0 ? xv[3].x : kk == 1 ? xv[3].y : kk == 2 ? xv[3].z : xv[3].w };
                #pragma unroll
                for (int t = 0; t < TN; t++)
                    #pragma unroll
                    for (int r = 0; r < 4; r++)
                        acc[r][t] = fmaf(xs[r], wv[t], acc[r][t]);
            }
        }
        #pragma unroll
        for (int r = 0; r < 4; r++) {
            int row = row0 + r;
            if (row < N) {
                float dsr = g_dis[row];
                #pragma unroll
                for (int t = 0; t < TN; t++)
                    O[(size_t)row * M + cg * TN + t] = acc[r][t] * dsr;
            }
        }
    }
}

// ---- gather core: plain sum of pre-scaled features -------------------------
template <int L>
__device__ __forceinline__ float4 gather_sum(const float4* __restrict__ Hv,
                                             const int4* __restrict__ C4,
                                             int pc, int lane) {
    float4 acc = make_float4(0.f, 0.f, 0.f, 0.f);
    for (int j = 0; j < pc; j++) {
        int4 a = __ldg(&C4[j]);
        float4 h0 = __ldg(&Hv[(size_t)a.x * L + lane]);
        float4 h1 = __ldg(&Hv[(size_t)a.y * L + lane]);
        float4 h2 = __ldg(&Hv[(size_t)a.z * L + lane]);
        float4 h3 = __ldg(&Hv[(size_t)a.w * L + lane]);
        acc.x += (h0.x + h1.x) + (h2.x + h3.x);
        acc.y += (h0.y + h1.y) + (h2.y + h3.y);
        acc.z += (h0.z + h1.z) + (h2.z + h3.z);
        acc.w += (h0.w + h1.w) + (h2.w + h3.w);
    }
    return acc;
}

// ---------------------------------------------------------------------------
__global__ void __launch_bounds__(TPB, 5) k_mega(
        const float* __restrict__ x, const void* __restrict__ ei,
        const float* __restrict__ W1, const float* __restrict__ b1,
        const float* __restrict__ W2, const float* __restrict__ b2,
        const float* __restrict__ W3, const float* __restrict__ b3,
        float* __restrict__ out, int N, int E) {
    __shared__ SM sm;
    int gtid = blockIdx.x * TPB + threadIdx.x;
    int lane = threadIdx.x & 31;

    // warp-parallel dtype detect (first 64 int64 values), per block
    if (threadIdx.x < 32) {
        const long long* p = (const long long*)ei;
        long long v0 = p[threadIdx.x], v1 = p[32 + threadIdx.x];
        int ok = (v0 >= 0 && v0 < (long long)N && v1 >= 0 && v1 < (long long)N);
        unsigned m = __ballot_sync(0xffffffffu, ok);
        if (threadIdx.x == 0) sm.is64 = (m == 0xffffffffu);
    }
    __syncthreads();
    int is64 = sm.is64;

    // Phase A: degree histogram (deg pre-zeroed by previous run)
    for (int e = gtid; e < E; e += NTH)
        atomicAdd(&g_deg[edge_at(ei, (size_t)E + e, is64)], 1);
    gsync(1u * NB);

    // Phase B: warp-aggregated bump allocation + dis + pad entries (= self)
    {
        int nround = ((N + NTH - 1) / NTH) * NTH;
        for (int i = gtid; i < nround; i += NTH) {
            int d = (i < N) ? g_deg[i] : 0;
            int pad = (i < N) ? ((d + 3) & ~3) : 0;
            int incl = pad;
            #pragma unroll
            for (int off = 1; off < 32; off <<= 1) {
                int v = __shfl_up_sync(0xffffffffu, incl, off);
                if (lane >= off) incl += v;
            }
            int total = __shfl_sync(0xffffffffu, incl, 31);
            int base;
            if (lane == 31) base = atomicAdd(&g_alloc, total);
            base = __shfl_sync(0xffffffffu, base, 31);
            if (i < N) {
                int st = base + incl - pad;
                g_rowptr[i] = st;
                g_dis[i] = rsqrtf((float)(d + 1));
                for (int j = d; j < pad; j++) g_csr[st + j] = i;
            }
        }
    }
    gsync(2u * NB);

    // Phase C: GEMM1 (x @ W1, scaled by dis) + CSR fill (independent work)
    gemm_phase<64, 64>(x, W1, g_h, N, &sm, 0);
    for (int e = gtid; e < E; e += NTH) {
        int s = edge_at(ei, e, is64);
        int d = edge_at(ei, (size_t)E + e, is64);
        int pos = atomicAdd(&g_cursor[d], 1);
        g_csr[g_rowptr[d] + pos] = s;
    }
    gsync(3u * NB);

    // Phase D: gather1 -> o1 = tanh(dis*(sum + (1-pad)*hs_self) + b1)
    for (int i = gtid; i < N; i += NTH) g_cursor[i] = 0;   // re-zero for next run
    {
        const float4* Hv = (const float4*)g_h;
        const float4* bv4 = (const float4*)b1;
        long long items = (long long)N * 16;
        for (long long it = gtid; it < items; it += NTH) {
            int node = (int)(it >> 4);
            int ln = (int)(it & 15);
            int d = g_deg[node];
            int pc = (d + 3) >> 2;
            float coef = 1.0f - (float)((pc << 2) - d);
            float4 acc = gather_sum<16>(Hv, (const int4*)(g_csr + g_rowptr[node]), pc, ln);
            float4 hs = __ldg(&Hv[(size_t)node * 16 + ln]);
            acc.x = fmaf(hs.x, coef, acc.x);
            acc.y = fmaf(hs.y, coef, acc.y);
            acc.z = fmaf(hs.z, coef, acc.z);
            acc.w = fmaf(hs.w, coef, acc.w);
            float dsn = g_dis[node];
            float4 bv = __ldg(&bv4[ln]);
            float4 o;
            o.x = fast_tanh(fmaf(acc.x, dsn, bv.x));
            o.y = fast_tanh(fmaf(acc.y, dsn, bv.y));
            o.z = fast_tanh(fmaf(acc.z, dsn, bv.z));
            o.w = fast_tanh(fmaf(acc.w, dsn, bv.w));
            ((float4*)g_o)[(size_t)node * 16 + ln] = o;
        }
    }
    gsync(4u * NB);

    // Phase E: GEMM2 (o1 @ W2, scaled by dis) -> g_h
    gemm_phase<64, 32>(g_o, W2, g_h, N, &sm, 1);
    gsync(5u * NB);

    // Phase F: gather2 + tanh + fused projection; store hs3 = dis*(o2.W3)
    {
        const float4* Hv = (const float4*)g_h;
        const float4* bv4 = (const float4*)b2;
        const float4* w34 = (const float4*)W3;
        int lane8 = lane & 7;
        float4 w3 = __ldg(&w34[lane8]);
        long long items = (long long)N * 8;
        long long chunks = (items + 31) >> 5;
        long long gw = gtid >> 5;
        long long warps = (long long)NTH >> 5;
        for (long long c = gw; c < chunks; c += warps) {
            long long it = (c << 5) + lane;
            bool act = it < items;
            float partial = 0.f;
            int node = 0;
            float dsn = 0.f;
            if (act) {
                node = (int)(it >> 3);
                int l = (int)(it & 7);
                int d = g_deg[node];
                int pc = (d + 3) >> 2;
                float coef = 1.0f - (float)((pc << 2) - d);
                float4 acc = gather_sum<8>(Hv, (const int4*)(g_csr + g_rowptr[node]), pc, l);
                float4 hs = __ldg(&Hv[(size_t)node * 8 + l]);
                acc.x = fmaf(hs.x, coef, acc.x);
                acc.y = fmaf(hs.y, coef, acc.y);
                acc.z = fmaf(hs.z, coef, acc.z);
                acc.w = fmaf(hs.w, coef, acc.w);
                dsn = g_dis[node];
                float4 bv = __ldg(&bv4[l]);
                float4 o;
                o.x = fast_tanh(fmaf(acc.x, dsn, bv.x));
                o.y = fast_tanh(fmaf(acc.y, dsn, bv.y));
                o.z = fast_tanh(fmaf(acc.z, dsn, bv.z));
                o.w = fast_tanh(fmaf(acc.w, dsn, bv.w));
                partial = o.x * w3.x + o.y * w3.y + o.z * w3.z + o.w * w3.w;
            }
            partial += __shfl_down_sync(0xffffffffu, partial, 4, 8);
            partial += __shfl_down_sync(0xffffffffu, partial, 2, 8);
            partial += __shfl_down_sync(0xffffffffu, partial, 1, 8);
            if (act && lane8 == 0) g_o[node] = dsn * partial;
        }
    }
    gsync(6u * NB);

    // Phase G: scalar gather3; out = dis*(sum + hs3_self) + b3; zero deg
    {
        float bb = __ldg(b3);
        int wg = gtid >> 5;
        for (int n = wg; n < N; n += (NTH >> 5)) {
            int start = g_rowptr[n];
            int c = g_deg[n];
            float acc = 0.f;
            for (int j = lane; j < c; j += 32)
                acc += __ldg(&g_o[g_csr[start + j]]);
            #pragma unroll
            for (int off = 16; off; off >>= 1)
                acc += __shfl_down_sync(0xffffffffu, acc, off);
            if (lane == 0) {
                out[n] = fmaf(g_dis[n], acc + g_o[n], bb);
                g_deg[n] = 0;                    // restore invariant
            }
        }
    }

    // final arrival: last CTA resets counters for next graph replay
    __syncthreads();
    if (threadIdx.x == 0) {
        __threadfence();
        unsigned v = atomicAdd(&g_bar, 1u);
        if (v == 7u * NB - 1u) {
            g_bar = 0u; g_alloc = 0;
            g_work[0] = 0; g_work[1] = 0; g_work[2] = 0; g_work[3] = 0;
        }
    }
}

// ---------------------------------------------------------------------------
extern "C" void kernel_launch(void* const* d_in, const int* in_sizes, int n_in,
                              void* d_out, int out_size) {
    const float* x  = (const float*)d_in[0];
    const void*  ei = d_in[1];
    const float* W1 = (const float*)d_in[2];
    const float* b1 = (const float*)d_in[3];
    const float* W2 = (const float*)d_in[4];
    const float* b2 = (const float*)d_in[5];
    const float* W3 = (const float*)d_in[6];
    const float* b3 = (const float*)d_in[7];
    float* out = (float*)d_out;

    int N = in_sizes[0] / 64;
    int E = in_sizes[1] / 2;

    k_mega<<<NB, TPB>>>(x, ei, W1, b1, W2, b2, W3, b3, out, N, E);
}

// round 10
// speedup vs baseline: 1.7790x; 1.1258x over previous
#include <cuda_runtime.h>
#include <cuda_fp16.h>

// ---------------------------------------------------------------------------
// 3-layer GCN persistent megakernel, round 9:
//  - fp16 feature storage for aggregation inputs (GEMM epilogue converts);
//    gather reads 8 halves per 16B load -> half the lanes, loads, and traffic
//  - fp32 accumulation everywhere; inter-layer activations (o1) stay fp32
//  - otherwise round-8 structure: 4B CSR w/ self-pads, warp-agg alloc,
//    static free-running gathers, dynamic GEMM tiles, deferred zeroing
// ---------------------------------------------------------------------------

#define NMAX 100000
#define EMAX 1600000
#define CSRMAX (EMAX + 4 * NMAX)
#define NB  740          // 148 SMs x 5 CTAs
#define TPB 256
#define NTH (NB * TPB)

__device__ unsigned g_bar;        // zero-init; restored to 0 at exit
__device__ int   g_alloc;         // restored at exit
__device__ int   g_work[8];       // GEMM tile counters; restored at exit
__device__ int   g_deg[NMAX];     // zeroed by previous run's final phase
__device__ int   g_rowptr[NMAX];
__device__ int   g_cursor[NMAX];  // zeroed by previous run's gather1 phase
__device__ float g_dis[NMAX];
__device__ __align__(16) int g_csr[CSRMAX];     // src indices; pads = dst itself
__device__ __align__(16) __half g_h16[(size_t)NMAX * 64];  // fp16 features
__device__ float g_o[(size_t)NMAX * 64];

struct SM {
    __align__(16) float w[4096];
    int tile;
    int is64;
};

__device__ __forceinline__ float fast_tanh(float x) {
    float y;
    asm("tanh.approx.f32 %0, %1;" : "=f"(y) : "f"(x));
    return y;
}

__device__ __forceinline__ void gsync(unsigned target) {
    __syncthreads();
    if (threadIdx.x == 0) {
        __threadfence();
        atomicAdd(&g_bar, 1u);
        while (*((volatile unsigned*)&g_bar) < target) __nanosleep(64);
    }
    __syncthreads();
}

__device__ __forceinline__ int edge_at(const void* ei, size_t idx, int is64) {
    if (is64) return (int)((const long long*)ei)[idx];
    return ((const int*)ei)[idx];
}

// unpack 8 halves (uint4) and add into fp32 accumulators
__device__ __forceinline__ void h8_acc(float* acc, uint4 q) {
    float2 t;
    t = __half22float2(*(__half2*)&q.x); acc[0] += t.x; acc[1] += t.y;
    t = __half22float2(*(__half2*)&q.y); acc[2] += t.x; acc[3] += t.y;
    t = __half22float2(*(__half2*)&q.z); acc[4] += t.x; acc[5] += t.y;
    t = __half22float2(*(__half2*)&q.w); acc[6] += t.x; acc[7] += t.y;
}
__device__ __forceinline__ void h8_unpack(uint4 q, float* f) {
    float2 t;
    t = __half22float2(*(__half2*)&q.x); f[0] = t.x; f[1] = t.y;
    t = __half22float2(*(__half2*)&q.y); f[2] = t.x; f[3] = t.y;
    t = __half22float2(*(__half2*)&q.z); f[4] = t.x; f[5] = t.y;
    t = __half22float2(*(__half2*)&q.w); f[6] = t.x; f[7] = t.y;
}

// ---- GEMM: O16[N,M] = fp16( dis[row] * (X[N,K] @ W[K,M]) ), dyn 64-row tiles
template <int K, int M>
__device__ void gemm_phase(const float* __restrict__ X, const float* __restrict__ W,
                           __half* __restrict__ O16, int N, SM* sm, int workid) {
    constexpr int TN = M / 16;
    for (int i = threadIdx.x; i < K * M; i += TPB) sm->w[i] = W[i];
    int cg = threadIdx.x & 15;
    int rg = threadIdx.x >> 4;
    int tiles = (N + 63) >> 6;
    const float4* __restrict__ X4 = (const float4*)X;
    for (;;) {
        __syncthreads();
        if (threadIdx.x == 0) sm->tile = atomicAdd(&g_work[workid], 1);
        __syncthreads();
        int tile = sm->tile;
        if (tile >= tiles) break;
        int row0 = tile * 64 + rg * 4;
        bool full = (row0 + 3 < N);
        float acc[4][TN];
        #pragma unroll
        for (int r = 0; r < 4; r++)
            #pragma unroll
            for (int t = 0; t < TN; t++) acc[r][t] = 0.f;
        #pragma unroll 2
        for (int k4 = 0; k4 < K / 4; k4++) {
            float4 xv[4];
            #pragma unroll
            for (int r = 0; r < 4; r++) {
                int row = row0 + r;
                if (full || row < N) xv[r] = __ldg(&X4[(size_t)row * (K / 4) + k4]);
                else xv[r] = make_float4(0.f, 0.f, 0.f, 0.f);
            }
            #pragma unroll
            for (int kk = 0; kk < 4; kk++) {
                int k = k4 * 4 + kk;
                float wv[TN];
                if (TN == 4) {
                    float4 wq = ((const float4*)sm->w)[k * (M / 4) + cg];
                    wv[0] = wq.x; wv[1] = wq.y; wv[2] = wq.z; wv[3] = wq.w;
                } else {
                    float2 wq = ((const float2*)sm->w)[k * (M / 2) + cg];
                    wv[0] = wq.x; wv[1] = wq.y;
                }
                float xs[4] = { kk == 0 ? xv[0].x : kk == 1 ? xv[0].y : kk == 2 ? xv[0].z : xv[0].w,
                                kk == 0 ? xv[1].x : kk == 1 ? xv[1].y : kk == 2 ? xv[1].z : xv[1].w,
                                kk == 0 ? xv[2].x : kk == 1 ? xv[2].y : kk == 2 ? xv[2].z : xv[2].w,
                                kk == 0 ? xv[3].x : kk == 1 ? xv[3].y : kk == 2 ? xv[3].z : xv[3].w };
                #pragma unroll
                for (int t = 0; t < TN; t++)
                    #pragma unroll
                    for (int r = 0; r < 4; r++)
                        acc[r][t] = fmaf(xs[r], wv[t], acc[r][t]);
            }
        }
        #pragma unroll
        for (int r = 0; r < 4; r++) {
            int row = row0 + r;
            if (row < N) {
                float dsr = g_dis[row];
                if (TN == 4) {
                    __half2 p0 = __floats2half2_rn(acc[r][0] * dsr, acc[r][1] * dsr);
                    __half2 p1 = __floats2half2_rn(acc[r][2] * dsr, acc[r][3] * dsr);
                    uint2 st;
                    st.x = *(unsigned*)&p0;
                    st.y = *(unsigned*)&p1;
                    *(uint2*)(O16 + (size_t)row * M + cg * 4) = st;
                } else {
                    __half2 p = __floats2half2_rn(acc[r][0] * dsr, acc[r][1] * dsr);
                    *(__half2*)(O16 + (size_t)row * M + cg * 2) = p;
                }
            }
        }
    }
}

// ---------------------------------------------------------------------------
__global__ void __launch_bounds__(TPB, 5) k_mega(
        const float* __restrict__ x, const void* __restrict__ ei,
        const float* __restrict__ W1, const float* __restrict__ b1,
        const float* __restrict__ W2, const float* __restrict__ b2,
        const float* __restrict__ W3, const float* __restrict__ b3,
        float* __restrict__ out, int N, int E) {
    __shared__ SM sm;
    int gtid = blockIdx.x * TPB + threadIdx.x;
    int lane = threadIdx.x & 31;

    // warp-parallel dtype detect (first 64 int64 values), per block
    if (threadIdx.x < 32) {
        const long long* p = (const long long*)ei;
        long long v0 = p[threadIdx.x], v1 = p[32 + threadIdx.x];
        int ok = (v0 >= 0 && v0 < (long long)N && v1 >= 0 && v1 < (long long)N);
        unsigned m = __ballot_sync(0xffffffffu, ok);
        if (threadIdx.x == 0) sm.is64 = (m == 0xffffffffu);
    }
    __syncthreads();
    int is64 = sm.is64;

    // Phase A: degree histogram (deg pre-zeroed by previous run)
    for (int e = gtid; e < E; e += NTH)
        atomicAdd(&g_deg[edge_at(ei, (size_t)E + e, is64)], 1);
    gsync(1u * NB);

    // Phase B: warp-aggregated bump allocation + dis + pad entries (= self)
    {
        int nround = ((N + NTH - 1) / NTH) * NTH;
        for (int i = gtid; i < nround; i += NTH) {
            int d = (i < N) ? g_deg[i] : 0;
            int pad = (i < N) ? ((d + 3) & ~3) : 0;
            int incl = pad;
            #pragma unroll
            for (int off = 1; off < 32; off <<= 1) {
                int v = __shfl_up_sync(0xffffffffu, incl, off);
                if (lane >= off) incl += v;
            }
            int total = __shfl_sync(0xffffffffu, incl, 31);
            int base;
            if (lane == 31) base = atomicAdd(&g_alloc, total);
            base = __shfl_sync(0xffffffffu, base, 31);
            if (i < N) {
                int st = base + incl - pad;
                g_rowptr[i] = st;
                g_dis[i] = rsqrtf((float)(d + 1));
                for (int j = d; j < pad; j++) g_csr[st + j] = i;
            }
        }
    }
    gsync(2u * NB);

    // Phase C: GEMM1 (x @ W1 -> fp16, scaled by dis) + CSR fill
    gemm_phase<64, 64>(x, W1, g_h16, N, &sm, 0);
    for (int e = gtid; e < E; e += NTH) {
        int s = edge_at(ei, e, is64);
        int d = edge_at(ei, (size_t)E + e, is64);
        int pos = atomicAdd(&g_cursor[d], 1);
        g_csr[g_rowptr[d] + pos] = s;
    }
    gsync(3u * NB);

    // Phase D: gather1 (fp16 in, fp32 accum) -> o1 fp32; 8 lanes per node
    for (int i = gtid; i < N; i += NTH) g_cursor[i] = 0;   // re-zero for next run
    {
        const uint4* __restrict__ Hq = (const uint4*)g_h16;   // 8 uint4 per node
        long long items = (long long)N * 8;
        for (long long it = gtid; it < items; it += NTH) {
            int node = (int)(it >> 3);
            int l = (int)(it & 7);
            int d = g_deg[node];
            int pc = (d + 3) >> 2;
            float coef = 1.0f - (float)((pc << 2) - d);
            const int4* __restrict__ C4 = (const int4*)(g_csr + g_rowptr[node]);
            float acc[8] = {0.f, 0.f, 0.f, 0.f, 0.f, 0.f, 0.f, 0.f};
            for (int j = 0; j < pc; j++) {
                int4 a = __ldg(&C4[j]);
                uint4 q0 = __ldg(&Hq[(size_t)a.x * 8 + l]);
                uint4 q1 = __ldg(&Hq[(size_t)a.y * 8 + l]);
                uint4 q2 = __ldg(&Hq[(size_t)a.z * 8 + l]);
                uint4 q3 = __ldg(&Hq[(size_t)a.w * 8 + l]);
                h8_acc(acc, q0); h8_acc(acc, q1); h8_acc(acc, q2); h8_acc(acc, q3);
            }
            uint4 qs = __ldg(&Hq[(size_t)node * 8 + l]);
            float s[8]; h8_unpack(qs, s);
            #pragma unroll
            for (int k = 0; k < 8; k++) acc[k] = fmaf(s[k], coef, acc[k]);
            float dsn = g_dis[node];
            float4 ba = __ldg(((const float4*)b1) + 2 * l);
            float4 bb = __ldg(((const float4*)b1) + 2 * l + 1);
            float bv[8] = {ba.x, ba.y, ba.z, ba.w, bb.x, bb.y, bb.z, bb.w};
            float o[8];
            #pragma unroll
            for (int k = 0; k < 8; k++) o[k] = fast_tanh(fmaf(acc[k], dsn, bv[k]));
            float4* dst = (float4*)(g_o + (size_t)node * 64 + l * 8);
            dst[0] = make_float4(o[0], o[1], o[2], o[3]);
            dst[1] = make_float4(o[4], o[5], o[6], o[7]);
        }
    }
    gsync(4u * NB);

    // Phase E: GEMM2 (o1 @ W2 -> fp16, scaled by dis) -> g_h16
    gemm_phase<64, 32>(g_o, W2, g_h16, N, &sm, 1);
    gsync(5u * NB);

    // Phase F: gather2 + tanh + fused projection; 4 lanes per node;
    //          store hs3 = dis*(o2.W3) into g_o[node]
    {
        const uint4* __restrict__ Hq = (const uint4*)g_h16;   // 4 uint4 per node
        long long items = (long long)N * 4;
        for (long long it = gtid; it < items; it += NTH) {
            int node = (int)(it >> 2);
            int l = (int)(it & 3);
            int d = g_deg[node];
            int pc = (d + 3) >> 2;
            float coef = 1.0f - (float)((pc << 2) - d);
            const int4* __restrict__ C4 = (const int4*)(g_csr + g_rowptr[node]);
            float acc[8] = {0.f, 0.f, 0.f, 0.f, 0.f, 0.f, 0.f, 0.f};
            for (int j = 0; j < pc; j++) {
                int4 a = __ldg(&C4[j]);
                uint4 q0 = __ldg(&Hq[(size_t)a.x * 4 + l]);
                uint4 q1 = __ldg(&Hq[(size_t)a.y * 4 + l]);
                uint4 q2 = __ldg(&Hq[(size_t)a.z * 4 + l]);
                uint4 q3 = __ldg(&Hq[(size_t)a.w * 4 + l]);
                h8_acc(acc, q0); h8_acc(acc, q1); h8_acc(acc, q2); h8_acc(acc, q3);
            }
            uint4 qs = __ldg(&Hq[(size_t)node * 4 + l]);
            float s[8]; h8_unpack(qs, s);
            #pragma unroll
            for (int k = 0; k < 8; k++) acc[k] = fmaf(s[k], coef, acc[k]);
            float dsn = g_dis[node];
            float4 ba = __ldg(((const float4*)b2) + 2 * l);
            float4 bb = __ldg(((const float4*)b2) + 2 * l + 1);
            float bv[8] = {ba.x, ba.y, ba.z, ba.w, bb.x, bb.y, bb.z, bb.w};
            float4 wa = __ldg(((const float4*)W3) + 2 * l);
            float4 wb = __ldg(((const float4*)W3) + 2 * l + 1);
            float wv[8] = {wa.x, wa.y, wa.z, wa.w, wb.x, wb.y, wb.z, wb.w};
            float partial = 0.f;
            #pragma unroll
            for (int k = 0; k < 8; k++)
                partial += fast_tanh(fmaf(acc[k], dsn, bv[k])) * wv[k];
            // reduce across the 4 lanes of this node (it&3 == laneid&3)
            partial += __shfl_down_sync(0xffffffffu, partial, 2, 4);
            partial += __shfl_down_sync(0xffffffffu, partial, 1, 4);
            if (l == 0) g_o[node] = dsn * partial;
        }
    }
    gsync(6u * NB);

    // Phase G: scalar gather3; out = dis*(sum + hs3_self) + b3; zero deg
    {
        float bb = __ldg(b3);
        int wg = gtid >> 5;
        for (int n = wg; n < N; n += (NTH >> 5)) {
            int start = g_rowptr[n];
            int c = g_deg[n];
            float acc = 0.f;
            for (int j = lane; j < c; j += 32)
                acc += __ldg(&g_o[g_csr[start + j]]);
            #pragma unroll
            for (int off = 16; off; off >>= 1)
                acc += __shfl_down_sync(0xffffffffu, acc, off);
            if (lane == 0) {
                out[n] = fmaf(g_dis[n], acc + g_o[n], bb);
                g_deg[n] = 0;                    // restore invariant
            }
        }
    }

    // final arrival: last CTA resets counters for next graph replay
    __syncthreads();
    if (threadIdx.x == 0) {
        __threadfence();
        unsigned v = atomicAdd(&g_bar, 1u);
        if (v == 7u * NB - 1u) {
            g_bar = 0u; g_alloc = 0;
            g_work[0] = 0; g_work[1] = 0; g_work[2] = 0; g_work[3] = 0;
        }
    }
}

// ---------------------------------------------------------------------------
extern "C" void kernel_launch(void* const* d_in, const int* in_sizes, int n_in,
                              void* d_out, int out_size) {
    const float* x  = (const float*)d_in[0];
    const void*  ei = d_in[1];
    const float* W1 = (const float*)d_in[2];
    const float* b1 = (const float*)d_in[3];
    const float* W2 = (const float*)d_in[4];
    const float* b2 = (const float*)d_in[5];
    const float* W3 = (const float*)d_in[6];
    const float* b3 = (const float*)d_in[7];
    float* out = (float*)d_out;

    int N = in_sizes[0] / 64;
    int E = in_sizes[1] / 2;

    k_mega<<<NB, TPB>>>(x, ei, W1, b1, W2, b2, W3, b3, out, N, E);
}